// round 5
// baseline (speedup 1.0000x reference)
#include <cuda_runtime.h>
#include <cuda_bf16.h>
#include <cstdint>

#define NN      50000
#define NE      800000
#define NRELS   200

// -------- scratch (device globals; allocation is forbidden) --------
__device__ int          g_cnt[NN];           // dst degree (re-zeroed by k_agg each call)
__device__ int          g_off[NN];           // exclusive offsets; advanced to segment end by scatter
__device__ unsigned int g_key[NE];           // (src | etype<<16) sorted by dst
__device__ float        g_rr[NRELS * 128];   // interleaved (rel, relB): lane l -> (r2l, r2l+1, rb2l, rb2l+1)
__device__ float        g_A[NN * 64];        // (sum h)/cnt
__device__ float        g_B[NN * 64];        // (sum h*r)/cnt
__device__ float        g_C[NN * 64];        // (sum relB)/cnt

// -------- f32x2 helpers --------
#define FMA2(acc, a, b) \
    asm("fma.rn.f32x2 %0, %1, %2, %0;" : "+l"(acc) : "l"(a), "l"(b))
#define PACK_DUP(h2, h) \
    asm("mov.b64 %0, {%1, %1};" : "=l"(h2) : "f"(h))
#define UNPACK2(lo, hi, v) \
    asm("mov.b64 {%0, %1}, %2;" : "=f"(lo), "=f"(hi) : "l"(v))

// -------- K1: relB + interleaved (rel, relB) table --------
__global__ void k_relB(const float* __restrict__ rel, const float* __restrict__ Wn) {
    int t = blockIdx.x;
    int j = threadIdx.x;           // 0..63
    float s = 0.0f;
    #pragma unroll 8
    for (int k = 0; k < 64; k++)
        s += rel[t * 64 + k] * (Wn[k * 64 + j] + Wn[(192 + k) * 64 + j]);
    int base = t * 128 + (j >> 1) * 4 + (j & 1);
    g_rr[base]     = rel[t * 64 + j];   // r at slots 0,1
    g_rr[base + 2] = s;                 // relB at slots 2,3
}

// -------- K2: dst degree histogram --------
__global__ void k_deg(const int* __restrict__ dst, int E) {
    int i = blockIdx.x * blockDim.x + threadIdx.x;
    int stride = gridDim.x * blockDim.x;
    int n4 = E >> 2;
    const int4* d4 = (const int4*)dst;
    for (int j = i; j < n4; j += stride) {
        int4 v = d4[j];
        atomicAdd(&g_cnt[v.x], 1);
        atomicAdd(&g_cnt[v.y], 1);
        atomicAdd(&g_cnt[v.z], 1);
        atomicAdd(&g_cnt[v.w], 1);
    }
    if (i < (E & 3)) atomicAdd(&g_cnt[dst[(n4 << 2) + i]], 1);
}

// -------- K3: single-block exclusive scan of g_cnt -> g_off --------
#define SCHUNK 49
__global__ __launch_bounds__(1024) void k_scan() {
    __shared__ int wsum[32];
    int tid = threadIdx.x;
    int lane = tid & 31, wid = tid >> 5;
    int base = tid * SCHUNK;
    int lim = min(base + SCHUNK, NN);
    int s = 0;
    for (int j = base; j < lim; j++) s += g_cnt[j];
    int x = s;
    #pragma unroll
    for (int d = 1; d < 32; d <<= 1) {
        int y = __shfl_up_sync(0xffffffffu, x, d);
        if (lane >= d) x += y;
    }
    if (lane == 31) wsum[wid] = x;
    __syncthreads();
    if (wid == 0) {
        int y = wsum[lane];
        int z = y;
        #pragma unroll
        for (int d = 1; d < 32; d <<= 1) {
            int t = __shfl_up_sync(0xffffffffu, z, d);
            if (lane >= d) z += t;
        }
        wsum[lane] = z - y;
    }
    __syncthreads();
    int run = (x - s) + wsum[wid];
    for (int j = base; j < lim; j++) {
        int c = g_cnt[j];
        g_off[j] = run;
        run += c;
    }
}

// -------- K4: counting-sort scatter by dst --------
__global__ void k_scatter(const int* __restrict__ src, const int* __restrict__ dst,
                          const int* __restrict__ et, int E) {
    int i = blockIdx.x * blockDim.x + threadIdx.x;
    int stride = gridDim.x * blockDim.x;
    int n4 = E >> 2;
    const int4* s4 = (const int4*)src;
    const int4* d4 = (const int4*)dst;
    const int4* t4 = (const int4*)et;
    for (int j = i; j < n4; j += stride) {
        int4 s = s4[j];
        int4 d = d4[j];
        int4 t = t4[j];
        int p0 = atomicAdd(&g_off[d.x], 1);
        int p1 = atomicAdd(&g_off[d.y], 1);
        int p2 = atomicAdd(&g_off[d.z], 1);
        int p3 = atomicAdd(&g_off[d.w], 1);
        g_key[p0] = (unsigned)s.x | ((unsigned)t.x << 16);
        g_key[p1] = (unsigned)s.y | ((unsigned)t.y << 16);
        g_key[p2] = (unsigned)s.z | ((unsigned)t.z << 16);
        g_key[p3] = (unsigned)s.w | ((unsigned)t.w << 16);
    }
    if (i < (E & 3)) {
        int e = (n4 << 2) + i;
        int p = atomicAdd(&g_off[dst[e]], 1);
        g_key[p] = (unsigned)src[e] | ((unsigned)et[e] << 16);
    }
}

// -------- K5: per-dst aggregation: warp/node, 4 edges/iter, branch-free masks --------
__global__ __launch_bounds__(256) void k_agg(const float* __restrict__ feat) {
    int w = (blockIdx.x * 256 + threadIdx.x) >> 5;
    if (w >= NN) return;
    int lane = threadIdx.x & 31;
    int beg = w ? g_off[w - 1] : 0;     // g_off[j] is now segment end; g_off[j-1] is begin
    int end = g_off[w];
    if (lane == 0) g_cnt[w] = 0;        // re-zero for next replay

    const float2* f2  = (const float2*)feat;
    const float4* rr4 = (const float4*)g_rr;

    float2 a0 = {0.f, 0.f}, a1 = a0, a2 = a0, a3 = a0;
    float2 b0 = a0, b1 = a0, b2 = a0, b3 = a0;
    float2 c0 = a0, c1 = a0, c2 = a0, c3 = a0;

    int maxi = (end > beg) ? end - 1 : 0;
    unsigned k0 = 0, k1 = 0, k2 = 0, k3 = 0;
    if (beg < end) {
        k0 = g_key[beg];
        k1 = g_key[min(beg + 1, maxi)];
        k2 = g_key[min(beg + 2, maxi)];
        k3 = g_key[min(beg + 3, maxi)];
    }

    for (int i = beg; i < end; i += 4) {
        int rem = end - i;
        // prefetch next group's keys (clamped; values masked at use)
        int j = i + 4;
        unsigned nk0 = g_key[min(j,     maxi)];
        unsigned nk1 = g_key[min(j + 1, maxi)];
        unsigned nk2 = g_key[min(j + 2, maxi)];
        unsigned nk3 = g_key[min(j + 3, maxi)];

        float m1 = (rem > 1) ? 1.f : 0.f;
        float m2 = (rem > 2) ? 1.f : 0.f;
        float m3 = (rem > 3) ? 1.f : 0.f;

        float2 h0 = f2[(k0 & 0xffffu) * 32 + lane];
        float4 q0 = rr4[(k0 >> 16) * 32 + lane];
        float2 h1 = f2[(k1 & 0xffffu) * 32 + lane];
        float4 q1 = rr4[(k1 >> 16) * 32 + lane];
        float2 h2 = f2[(k2 & 0xffffu) * 32 + lane];
        float4 q2 = rr4[(k2 >> 16) * 32 + lane];
        float2 h3 = f2[(k3 & 0xffffu) * 32 + lane];
        float4 q3 = rr4[(k3 >> 16) * 32 + lane];

        // edge 0 always valid inside loop
        a0.x += h0.x;                      a0.y += h0.y;
        b0.x = fmaf(h0.x, q0.x, b0.x);     b0.y = fmaf(h0.y, q0.y, b0.y);
        c0.x += q0.z;                      c0.y += q0.w;

        float h1x = h1.x * m1, h1y = h1.y * m1;
        a1.x += h1x;                       a1.y += h1y;
        b1.x = fmaf(h1x, q1.x, b1.x);      b1.y = fmaf(h1y, q1.y, b1.y);
        c1.x = fmaf(q1.z, m1, c1.x);       c1.y = fmaf(q1.w, m1, c1.y);

        float h2x = h2.x * m2, h2y = h2.y * m2;
        a2.x += h2x;                       a2.y += h2y;
        b2.x = fmaf(h2x, q2.x, b2.x);      b2.y = fmaf(h2y, q2.y, b2.y);
        c2.x = fmaf(q2.z, m2, c2.x);       c2.y = fmaf(q2.w, m2, c2.y);

        float h3x = h3.x * m3, h3y = h3.y * m3;
        a3.x += h3x;                       a3.y += h3y;
        b3.x = fmaf(h3x, q3.x, b3.x);      b3.y = fmaf(h3y, q3.y, b3.y);
        c3.x = fmaf(q3.z, m3, c3.x);       c3.y = fmaf(q3.w, m3, c3.y);

        k0 = nk0; k1 = nk1; k2 = nk2; k3 = nk3;
    }

    float inv = 1.0f / fmaxf((float)(end - beg), 1.0f);
    float2 A = make_float2(((a0.x + a1.x) + (a2.x + a3.x)) * inv,
                           ((a0.y + a1.y) + (a2.y + a3.y)) * inv);
    float2 B = make_float2(((b0.x + b1.x) + (b2.x + b3.x)) * inv,
                           ((b0.y + b1.y) + (b2.y + b3.y)) * inv);
    float2 C = make_float2(((c0.x + c1.x) + (c2.x + c3.x)) * inv,
                           ((c0.y + c1.y) + (c2.y + c3.y)) * inv);
    int o = w * 32 + lane;
    ((float2*)g_A)[o] = A;
    ((float2*)g_B)[o] = B;
    ((float2*)g_C)[o] = C;
}

// -------- K6: out = A@W13 + B@W2 + C + feat@LW  (32 nodes / block, 256 thr) --------
#define TS 65
#define FSMEM ((3 * 4096 + 3 * 32 * TS) * 4)

__global__ __launch_bounds__(256) void k_final(const float* __restrict__ feat,
                                               const float* __restrict__ Wn,
                                               const float* __restrict__ LW,
                                               float* __restrict__ out, int N) {
    extern __shared__ float smem[];
    float* W13s = smem;                 // 4096
    float* W2s  = smem + 4096;          // 4096
    float* LWs  = smem + 8192;          // 4096
    float* As   = smem + 12288;         // 32*65
    float* Bs   = As + 32 * TS;
    float* Fs   = Bs + 32 * TS;

    int tid = threadIdx.x;
    for (int idx = tid; idx < 4096; idx += 256) {
        W13s[idx] = Wn[idx] + Wn[8192 + idx];
        W2s[idx]  = Wn[4096 + idx];
        LWs[idx]  = LW[idx];
    }

    int n0 = blockIdx.x * 32;
    #pragma unroll
    for (int p = 0; p < 6; p++) {
        int idx = p * 256 + tid;        // 0..1535 : matrix = idx/512, slot = idx%512
        int mat = idx >> 9;
        int slot = idx & 511;
        int e = slot >> 4, c4 = slot & 15;
        int node = n0 + e;
        const float* srcp = (mat == 0) ? g_A : (mat == 1) ? g_B : feat;
        float* dstp = (mat == 0) ? As : (mat == 1) ? Bs : Fs;
        float4 v = make_float4(0.f, 0.f, 0.f, 0.f);
        if (node < N) v = *(const float4*)&srcp[(size_t)node * 64 + c4 * 4];
        float* hp = &dstp[e * TS + c4 * 4];
        hp[0] = v.x; hp[1] = v.y; hp[2] = v.z; hp[3] = v.w;
    }
    __syncthreads();

    int ty = tid >> 3, tx = tid & 7, jj = tx * 8;
    int node = n0 + ty;

    unsigned long long a0 = 0, a1 = 0, a2 = 0, a3 = 0;
    #pragma unroll 4
    for (int k = 0; k < 64; k++) {
        float la = As[ty * TS + k];
        float lb = Bs[ty * TS + k];
        float lf = Fs[ty * TS + k];
        unsigned long long la2, lb2, lf2;
        PACK_DUP(la2, la); PACK_DUP(lb2, lb); PACK_DUP(lf2, lf);

        const float* w13 = &W13s[(k << 6) + jj];
        const float* w2  = &W2s[(k << 6) + jj];
        const float* lw  = &LWs[(k << 6) + jj];
        ulonglong2 wA = *reinterpret_cast<const ulonglong2*>(w13);
        ulonglong2 wB = *reinterpret_cast<const ulonglong2*>(w13 + 4);
        ulonglong2 vA = *reinterpret_cast<const ulonglong2*>(w2);
        ulonglong2 vB = *reinterpret_cast<const ulonglong2*>(w2 + 4);
        ulonglong2 uA = *reinterpret_cast<const ulonglong2*>(lw);
        ulonglong2 uB = *reinterpret_cast<const ulonglong2*>(lw + 4);

        FMA2(a0, la2, wA.x); FMA2(a1, la2, wA.y); FMA2(a2, la2, wB.x); FMA2(a3, la2, wB.y);
        FMA2(a0, lb2, vA.x); FMA2(a1, lb2, vA.y); FMA2(a2, lb2, vB.x); FMA2(a3, lb2, vB.y);
        FMA2(a0, lf2, uA.x); FMA2(a1, lf2, uA.y); FMA2(a2, lf2, uB.x); FMA2(a3, lf2, uB.y);
    }

    if (node < N) {
        float4 c0 = *(const float4*)&g_C[(size_t)node * 64 + jj];
        float4 c1 = *(const float4*)&g_C[(size_t)node * 64 + jj + 4];
        float v0, v1, v2, v3, v4, v5, v6, v7;
        UNPACK2(v0, v1, a0); UNPACK2(v2, v3, a1);
        UNPACK2(v4, v5, a2); UNPACK2(v6, v7, a3);
        float* p = out + (size_t)node * 64 + jj;
        *(float4*)p       = make_float4(v0 + c0.x, v1 + c0.y, v2 + c0.z, v3 + c0.w);
        *(float4*)(p + 4) = make_float4(v4 + c1.x, v5 + c1.y, v6 + c1.z, v7 + c1.w);
    }
}

// -------- launch --------
extern "C" void kernel_launch(void* const* d_in, const int* in_sizes, int n_in,
                              void* d_out, int out_size) {
    const float* feat = (const float*)d_in[0];
    const float* rel  = (const float*)d_in[1];
    const float* Wn   = (const float*)d_in[2];
    const float* LW   = (const float*)d_in[3];
    const int*   src  = (const int*)d_in[4];
    const int*   dst  = (const int*)d_in[5];
    const int*   et   = (const int*)d_in[6];
    float* out = (float*)d_out;

    int E = in_sizes[4];
    int N = in_sizes[0] / 64;

    cudaFuncSetAttribute(k_final, cudaFuncAttributeMaxDynamicSharedMemorySize, FSMEM);

    k_relB<<<NRELS, 64>>>(rel, Wn);
    k_deg<<<512, 256>>>(dst, E);
    k_scan<<<1, 1024>>>();
    k_scatter<<<800, 256>>>(src, dst, et, E);
    k_agg<<<(NN * 32 + 255) / 256, 256>>>(feat);
    k_final<<<(N + 31) / 32, 256, FSMEM>>>(feat, Wn, LW, out, N);
}

// round 6
// speedup vs baseline: 1.0964x; 1.0964x over previous
#include <cuda_runtime.h>
#include <cuda_bf16.h>
#include <cstdint>

#define NN      50000
#define NE      800000
#define NRELS   200

// -------- scratch (device globals; allocation is forbidden) --------
__device__ int          g_cnt[NN];           // dst degree (re-zeroed by k_agg each call)
__device__ int          g_off[NN];           // scan: exclusive offsets; scatter advances to segment end
__device__ unsigned int g_key[NE];           // (src | etype<<16) sorted by dst
__device__ float        g_rr[NRELS * 128];   // interleaved (rel, relB) per relation
__device__ float        g_A[NN * 64];        // (sum h)/cnt
__device__ float        g_B[NN * 64];        // (sum h*r)/cnt
__device__ float        g_C[NN * 64];        // (sum relB)/cnt

// -------- f32x2 helpers --------
#define FMA2(acc, a, b) \
    asm("fma.rn.f32x2 %0, %1, %2, %0;" : "+l"(acc) : "l"(a), "l"(b))
#define PACK_DUP(h2, h) \
    asm("mov.b64 %0, {%1, %1};" : "=l"(h2) : "f"(h))
#define UNPACK2(lo, hi, v) \
    asm("mov.b64 {%0, %1}, %2;" : "=f"(lo), "=f"(hi) : "l"(v))

// -------- K1: fused dst-degree histogram + relB table --------
// blocks 0..NRELS-1, threads 0..63 additionally compute relB row (t = blockIdx.x)
__global__ __launch_bounds__(256) void k_fused(const float* __restrict__ rel,
                                               const float* __restrict__ Wn,
                                               const int* __restrict__ dst, int E) {
    int b = blockIdx.x, tid = threadIdx.x;

    if (b < NRELS && tid < 64) {
        int t = b, j = tid;
        float s = 0.0f;
        #pragma unroll 8
        for (int k = 0; k < 64; k++)
            s += rel[t * 64 + k] * (Wn[k * 64 + j] + Wn[(192 + k) * 64 + j]);
        int base = t * 128 + (j >> 1) * 4 + (j & 1);
        g_rr[base]     = rel[t * 64 + j];   // rel at float4 slots .x/.y
        g_rr[base + 2] = s;                 // relB at slots .z/.w
    }

    int i = b * 256 + tid;
    int stride = gridDim.x * 256;
    int n4 = E >> 2;
    const int4* d4 = (const int4*)dst;
    for (int j = i; j < n4; j += stride) {
        int4 v = d4[j];
        atomicAdd(&g_cnt[v.x], 1);
        atomicAdd(&g_cnt[v.y], 1);
        atomicAdd(&g_cnt[v.z], 1);
        atomicAdd(&g_cnt[v.w], 1);
    }
    if (i < (E & 3)) atomicAdd(&g_cnt[dst[(n4 << 2) + i]], 1);
}

// -------- K2: single-block exclusive scan of g_cnt -> g_off --------
#define SCHUNK 49
__global__ __launch_bounds__(1024) void k_scan() {
    __shared__ int wsum[32];
    int tid = threadIdx.x;
    int lane = tid & 31, wid = tid >> 5;
    int base = tid * SCHUNK;
    int lim = min(base + SCHUNK, NN);
    int s = 0;
    for (int j = base; j < lim; j++) s += g_cnt[j];
    int x = s;
    #pragma unroll
    for (int d = 1; d < 32; d <<= 1) {
        int y = __shfl_up_sync(0xffffffffu, x, d);
        if (lane >= d) x += y;
    }
    if (lane == 31) wsum[wid] = x;
    __syncthreads();
    if (wid == 0) {
        int y = wsum[lane];
        int z = y;
        #pragma unroll
        for (int d = 1; d < 32; d <<= 1) {
            int t = __shfl_up_sync(0xffffffffu, z, d);
            if (lane >= d) z += t;
        }
        wsum[lane] = z - y;
    }
    __syncthreads();
    int run = (x - s) + wsum[wid];
    for (int j = base; j < lim; j++) {
        int c = g_cnt[j];
        g_off[j] = run;
        run += c;
    }
}

// -------- K3: counting-sort scatter by dst --------
__global__ void k_scatter(const int* __restrict__ src, const int* __restrict__ dst,
                          const int* __restrict__ et, int E) {
    int i = blockIdx.x * blockDim.x + threadIdx.x;
    int stride = gridDim.x * blockDim.x;
    int n4 = E >> 2;
    const int4* s4 = (const int4*)src;
    const int4* d4 = (const int4*)dst;
    const int4* t4 = (const int4*)et;
    for (int j = i; j < n4; j += stride) {
        int4 s = s4[j];
        int4 d = d4[j];
        int4 t = t4[j];
        int p0 = atomicAdd(&g_off[d.x], 1);
        int p1 = atomicAdd(&g_off[d.y], 1);
        int p2 = atomicAdd(&g_off[d.z], 1);
        int p3 = atomicAdd(&g_off[d.w], 1);
        g_key[p0] = (unsigned)s.x | ((unsigned)t.x << 16);
        g_key[p1] = (unsigned)s.y | ((unsigned)t.y << 16);
        g_key[p2] = (unsigned)s.z | ((unsigned)t.z << 16);
        g_key[p3] = (unsigned)s.w | ((unsigned)t.w << 16);
    }
    if (i < (E & 3)) {
        int e = (n4 << 2) + i;
        int p = atomicAdd(&g_off[dst[e]], 1);
        g_key[p] = (unsigned)src[e] | ((unsigned)et[e] << 16);
    }
}

// -------- K4: per-dst aggregation (R3 anchor loop: warp/node, 1 edge/iter) --------
__global__ __launch_bounds__(256) void k_agg(const float* __restrict__ feat) {
    int w = (blockIdx.x * 256 + threadIdx.x) >> 5;
    if (w >= NN) return;
    int lane = threadIdx.x & 31;
    int beg = w ? g_off[w - 1] : 0;   // after scatter, g_off[j] == segment end
    int end = g_off[w];
    if (lane == 0) g_cnt[w] = 0;      // re-zero for next replay (deterministic)

    const float2* f2  = (const float2*)feat;
    const float4* rr4 = (const float4*)g_rr;

    float ax = 0.f, ay = 0.f, bx = 0.f, by = 0.f, cx = 0.f, cy = 0.f;

    if (beg < end) {
        unsigned k = g_key[beg];
        for (int i = beg; i < end; i++) {
            unsigned kn = (i + 1 < end) ? g_key[i + 1] : k;   // 1-ahead key prefetch
            float2 h = f2[(k & 0xffffu) * 32 + lane];
            float4 q = rr4[(k >> 16) * 32 + lane];
            ax += h.x;  ay += h.y;
            bx = fmaf(h.x, q.x, bx);
            by = fmaf(h.y, q.y, by);
            cx += q.z;  cy += q.w;
            k = kn;
        }
    }
    float inv = 1.0f / fmaxf((float)(end - beg), 1.0f);
    int o = w * 32 + lane;
    ((float2*)g_A)[o] = make_float2(ax * inv, ay * inv);
    ((float2*)g_B)[o] = make_float2(bx * inv, by * inv);
    ((float2*)g_C)[o] = make_float2(cx * inv, cy * inv);
}

// -------- K5: out = A@W13 + B@W2 + C + feat@LW  (32 nodes / block, 256 thr) --------
#define TS 65
#define FSMEM ((3 * 4096 + 3 * 32 * TS) * 4)

__global__ __launch_bounds__(256) void k_final(const float* __restrict__ feat,
                                               const float* __restrict__ Wn,
                                               const float* __restrict__ LW,
                                               float* __restrict__ out, int N) {
    extern __shared__ float smem[];
    float* W13s = smem;                 // 4096
    float* W2s  = smem + 4096;          // 4096
    float* LWs  = smem + 8192;          // 4096
    float* As   = smem + 12288;         // 32*65
    float* Bs   = As + 32 * TS;
    float* Fs   = Bs + 32 * TS;

    int tid = threadIdx.x;
    for (int idx = tid; idx < 4096; idx += 256) {
        W13s[idx] = Wn[idx] + Wn[8192 + idx];
        W2s[idx]  = Wn[4096 + idx];
        LWs[idx]  = LW[idx];
    }

    int n0 = blockIdx.x * 32;
    #pragma unroll
    for (int p = 0; p < 6; p++) {
        int idx = p * 256 + tid;        // 0..1535 : matrix = idx/512, slot = idx%512
        int mat = idx >> 9;
        int slot = idx & 511;
        int e = slot >> 4, c4 = slot & 15;
        int node = n0 + e;
        const float* srcp = (mat == 0) ? g_A : (mat == 1) ? g_B : feat;
        float* dstp = (mat == 0) ? As : (mat == 1) ? Bs : Fs;
        float4 v = make_float4(0.f, 0.f, 0.f, 0.f);
        if (node < N) v = *(const float4*)&srcp[(size_t)node * 64 + c4 * 4];
        float* hp = &dstp[e * TS + c4 * 4];
        hp[0] = v.x; hp[1] = v.y; hp[2] = v.z; hp[3] = v.w;
    }
    __syncthreads();

    int ty = tid >> 3, tx = tid & 7, jj = tx * 8;
    int node = n0 + ty;

    unsigned long long a0 = 0, a1 = 0, a2 = 0, a3 = 0;
    #pragma unroll 4
    for (int k = 0; k < 64; k++) {
        float la = As[ty * TS + k];
        float lb = Bs[ty * TS + k];
        float lf = Fs[ty * TS + k];
        unsigned long long la2, lb2, lf2;
        PACK_DUP(la2, la); PACK_DUP(lb2, lb); PACK_DUP(lf2, lf);

        const float* w13 = &W13s[(k << 6) + jj];
        const float* w2  = &W2s[(k << 6) + jj];
        const float* lw  = &LWs[(k << 6) + jj];
        ulonglong2 wA = *reinterpret_cast<const ulonglong2*>(w13);
        ulonglong2 wB = *reinterpret_cast<const ulonglong2*>(w13 + 4);
        ulonglong2 vA = *reinterpret_cast<const ulonglong2*>(w2);
        ulonglong2 vB = *reinterpret_cast<const ulonglong2*>(w2 + 4);
        ulonglong2 uA = *reinterpret_cast<const ulonglong2*>(lw);
        ulonglong2 uB = *reinterpret_cast<const ulonglong2*>(lw + 4);

        FMA2(a0, la2, wA.x); FMA2(a1, la2, wA.y); FMA2(a2, la2, wB.x); FMA2(a3, la2, wB.y);
        FMA2(a0, lb2, vA.x); FMA2(a1, lb2, vA.y); FMA2(a2, lb2, vB.x); FMA2(a3, lb2, vB.y);
        FMA2(a0, lf2, uA.x); FMA2(a1, lf2, uA.y); FMA2(a2, lf2, uB.x); FMA2(a3, lf2, uB.y);
    }

    if (node < N) {
        float4 c0 = *(const float4*)&g_C[(size_t)node * 64 + jj];
        float4 c1 = *(const float4*)&g_C[(size_t)node * 64 + jj + 4];
        float v0, v1, v2, v3, v4, v5, v6, v7;
        UNPACK2(v0, v1, a0); UNPACK2(v2, v3, a1);
        UNPACK2(v4, v5, a2); UNPACK2(v6, v7, a3);
        float* p = out + (size_t)node * 64 + jj;
        *(float4*)p       = make_float4(v0 + c0.x, v1 + c0.y, v2 + c0.z, v3 + c0.w);
        *(float4*)(p + 4) = make_float4(v4 + c1.x, v5 + c1.y, v6 + c1.z, v7 + c1.w);
    }
}

// -------- launch --------
extern "C" void kernel_launch(void* const* d_in, const int* in_sizes, int n_in,
                              void* d_out, int out_size) {
    const float* feat = (const float*)d_in[0];
    const float* rel  = (const float*)d_in[1];
    const float* Wn   = (const float*)d_in[2];
    const float* LW   = (const float*)d_in[3];
    const int*   src  = (const int*)d_in[4];
    const int*   dst  = (const int*)d_in[5];
    const int*   et   = (const int*)d_in[6];
    float* out = (float*)d_out;

    int E = in_sizes[4];
    int N = in_sizes[0] / 64;

    cudaFuncSetAttribute(k_final, cudaFuncAttributeMaxDynamicSharedMemorySize, FSMEM);

    k_fused<<<512, 256>>>(rel, Wn, dst, E);          // launch 0
    k_scan<<<1, 1024>>>();                            // launch 1
    k_scatter<<<800, 256>>>(src, dst, et, E);         // launch 2
    k_agg<<<(NN * 32 + 255) / 256, 256>>>(feat);      // launch 3  <- ncu capture slot
    k_final<<<(N + 31) / 32, 256, FSMEM>>>(feat, Wn, LW, out, N);
}